// round 1
// baseline (speedup 1.0000x reference)
#include <cuda_runtime.h>
#include <cstdint>

#define NN 50000
#define DD 128
#define EE 800000
#define ND (NN*DD)

// Scratch (static __device__ allocation is the sanctioned mechanism).
// g_xw[0]=pos1, [1]=neg1, [2]=pos2, [3]=neg2
__device__ float g_xw[4][ND];
__device__ float g_dinv[2][NN];   // holds deg first, then rsqrt(deg) in place

// ---------------------------------------------------------------------------
// degree / norm kernels
// ---------------------------------------------------------------------------
__global__ void k_init_deg() {
    int i = blockIdx.x * blockDim.x + threadIdx.x;
    if (i < NN) { g_dinv[0][i] = 1.0f; g_dinv[1][i] = 1.0f; }
}

__global__ void k_count(const int* __restrict__ ei, int b) {
    int e = blockIdx.x * blockDim.x + threadIdx.x;
    if (e < EE) atomicAdd(&g_dinv[b][ei[EE + e]], 1.0f);   // dst row
}

__global__ void k_rsqrt() {
    int i = blockIdx.x * blockDim.x + threadIdx.x;
    if (i < 2 * NN) {
        float* p = &g_dinv[0][0];
        p[i] = rsqrtf(p[i]);
    }
}

// ---------------------------------------------------------------------------
// Masked (and optionally row-permuted) GEMM:  out = (x .* mask)[perm] @ W
// Tile: 64 rows x 128 cols per block of 256 threads, K chunked by 32.
// ---------------------------------------------------------------------------
__global__ __launch_bounds__(256) void k_gemm(const float* __restrict__ x,
                                              const float* __restrict__ mask,
                                              const int* __restrict__ perm,
                                              const float* __restrict__ W,
                                              int outIdx) {
    __shared__ float Ws[32 * 128];
    __shared__ float As[64 * 32];
    float4* Ws4 = reinterpret_cast<float4*>(Ws);
    float4* As4 = reinterpret_cast<float4*>(As);
    const float4* x4 = reinterpret_cast<const float4*>(x);
    const float4* m4 = reinterpret_cast<const float4*>(mask);
    const float4* W4 = reinterpret_cast<const float4*>(W);
    float4* out4 = reinterpret_cast<float4*>(g_xw[outIdx]);

    const int tid = threadIdx.x;
    const int c = tid & 31;     // col-thread -> cols [4c, 4c+4)
    const int g = tid >> 5;     // row group  -> rows [8g, 8g+8) of tile
    const int row0 = blockIdx.x * 64;

    float4 acc[8];
    #pragma unroll
    for (int r = 0; r < 8; r++) acc[r] = make_float4(0.f, 0.f, 0.f, 0.f);

    for (int kc = 0; kc < 128; kc += 32) {
        // load W chunk [32][128] : 1024 float4
        #pragma unroll
        for (int j = 0; j < 4; j++) {
            int idx = tid + 256 * j;
            int kk = idx >> 5, c4 = idx & 31;
            Ws4[idx] = W4[(kc + kk) * 32 + c4];
        }
        // load A chunk [64][32] : 512 float4, fused mask (+ optional gather)
        #pragma unroll
        for (int j = 0; j < 2; j++) {
            int idx = tid + 256 * j;
            int r = idx >> 3, c4 = idx & 7;
            int gi = row0 + r;
            float4 v = make_float4(0.f, 0.f, 0.f, 0.f);
            if (gi < NN) {
                int srow = perm ? perm[gi] : gi;
                int base = srow * 32 + (kc >> 2) + c4;
                float4 xv = x4[base];
                float4 mv = m4[base];
                v.x = xv.x * mv.x; v.y = xv.y * mv.y;
                v.z = xv.z * mv.z; v.w = xv.w * mv.w;
            }
            As4[idx] = v;
        }
        __syncthreads();
        #pragma unroll
        for (int k = 0; k < 32; k++) {
            float4 w = Ws4[k * 32 + c];
            #pragma unroll
            for (int r = 0; r < 8; r++) {
                float a = As[(8 * g + r) * 32 + k];
                acc[r].x += a * w.x; acc[r].y += a * w.y;
                acc[r].z += a * w.z; acc[r].w += a * w.w;
            }
        }
        __syncthreads();
    }
    #pragma unroll
    for (int r = 0; r < 8; r++) {
        int gi = row0 + 8 * g + r;
        if (gi < NN) out4[gi * 32 + c] = acc[r];
    }
}

// ---------------------------------------------------------------------------
// Self-loop init: out[i,:] = xw[i,:] * dinv[i]^2   (writes every element)
// ---------------------------------------------------------------------------
__global__ void k_selfinit(int b, float* __restrict__ outp, float* __restrict__ outn) {
    int idx = blockIdx.x * blockDim.x + threadIdx.x;   // over N*32 float4
    if (idx >= NN * 32) return;
    int i = idx >> 5;
    float di = g_dinv[b][i];
    float s = di * di;
    const float4* xp = reinterpret_cast<const float4*>(g_xw[2 * b]);
    const float4* xn = reinterpret_cast<const float4*>(g_xw[2 * b + 1]);
    float4 vp = xp[idx], vn = xn[idx];
    vp.x *= s; vp.y *= s; vp.z *= s; vp.w *= s;
    vn.x *= s; vn.y *= s; vn.z *= s; vn.w *= s;
    reinterpret_cast<float4*>(outp)[idx] = vp;
    reinterpret_cast<float4*>(outn)[idx] = vn;
}

// ---------------------------------------------------------------------------
// Edge scatter: one warp per edge, lane = float4 chunk of the 128-wide row.
// Serves pos & neg of a branch in one pass (shared indices + norm).
// ---------------------------------------------------------------------------
__device__ __forceinline__ void red4(float4* p, float4 v) {
    asm volatile("red.global.add.v4.f32 [%0], {%1, %2, %3, %4};"
                 :: "l"(p), "f"(v.x), "f"(v.y), "f"(v.z), "f"(v.w) : "memory");
}

__global__ __launch_bounds__(256) void k_scatter(const int* __restrict__ ei, int b,
                                                 float* __restrict__ outp,
                                                 float* __restrict__ outn) {
    int t = blockIdx.x * blockDim.x + threadIdx.x;
    int e = t >> 5;
    int lane = t & 31;
    if (e >= EE) return;
    int s = ei[e];
    int d = ei[EE + e];
    float norm = g_dinv[b][s] * g_dinv[b][d];
    const float4* xp = reinterpret_cast<const float4*>(g_xw[2 * b]);
    const float4* xn = reinterpret_cast<const float4*>(g_xw[2 * b + 1]);
    float4 vp = xp[s * 32 + lane];
    vp.x *= norm; vp.y *= norm; vp.z *= norm; vp.w *= norm;
    red4(reinterpret_cast<float4*>(outp) + d * 32 + lane, vp);
    float4 vn = xn[s * 32 + lane];
    vn.x *= norm; vn.y *= norm; vn.z *= norm; vn.w *= norm;
    red4(reinterpret_cast<float4*>(outn) + d * 32 + lane, vn);
}

// ---------------------------------------------------------------------------
// Summary zero-init
// ---------------------------------------------------------------------------
__global__ void k_zeros(float* s1, float* s2) {
    int t = threadIdx.x;
    if (t < DD) { s1[t] = 0.f; s2[t] = 0.f; }
}

// ---------------------------------------------------------------------------
// Finalize: out = relu(out + bias); optional column-mean accumulation
// 64 rows per block of 256 threads.
// ---------------------------------------------------------------------------
__global__ __launch_bounds__(256) void k_finalize(float* __restrict__ out,
                                                  const float* __restrict__ bias,
                                                  float* __restrict__ summary,
                                                  float invN) {
    __shared__ float ssum[DD];
    const int tid = threadIdx.x;
    const int c4 = tid & 31;
    const int g = tid >> 5;
    const int row0 = blockIdx.x * 64;
    if (summary && tid < DD) ssum[tid] = 0.f;
    if (summary) __syncthreads();

    const float4* b4 = reinterpret_cast<const float4*>(bias);
    float4 bv = b4[c4];
    float4* out4 = reinterpret_cast<float4*>(out);
    float4 part = make_float4(0.f, 0.f, 0.f, 0.f);
    #pragma unroll
    for (int r = 0; r < 8; r++) {
        int row = row0 + g * 8 + r;
        if (row < NN) {
            float4 v = out4[row * 32 + c4];
            v.x = fmaxf(v.x + bv.x, 0.f);
            v.y = fmaxf(v.y + bv.y, 0.f);
            v.z = fmaxf(v.z + bv.z, 0.f);
            v.w = fmaxf(v.w + bv.w, 0.f);
            out4[row * 32 + c4] = v;
            part.x += v.x; part.y += v.y; part.z += v.z; part.w += v.w;
        }
    }
    if (summary) {
        atomicAdd(&ssum[4 * c4 + 0], part.x);
        atomicAdd(&ssum[4 * c4 + 1], part.y);
        atomicAdd(&ssum[4 * c4 + 2], part.z);
        atomicAdd(&ssum[4 * c4 + 3], part.w);
        __syncthreads();
        if (tid < DD) atomicAdd(&summary[tid], ssum[tid] * invN);
    }
}

// ---------------------------------------------------------------------------
extern "C" void kernel_launch(void* const* d_in, const int* in_sizes, int n_in,
                              void* d_out, int out_size) {
    const float* x   = (const float*)d_in[0];
    const float* W1  = (const float*)d_in[1];
    const float* b1  = (const float*)d_in[2];
    const float* W2  = (const float*)d_in[3];
    const float* b2  = (const float*)d_in[4];
    const float* mp1 = (const float*)d_in[5];
    const float* mn1 = (const float*)d_in[6];
    const float* mp2 = (const float*)d_in[7];
    const float* mn2 = (const float*)d_in[8];
    const int* e1    = (const int*)d_in[9];
    const int* e2    = (const int*)d_in[10];
    const int* perm1 = (const int*)d_in[11];
    const int* perm2 = (const int*)d_in[12];

    float* out = (float*)d_out;
    float* p1 = out;
    float* n1 = p1 + ND;
    float* s1 = n1 + ND;
    float* p2 = s1 + DD;
    float* n2 = p2 + ND;
    float* s2 = n2 + ND;

    const float invN = 1.0f / (float)NN;
    const int TB = 256;

    // degrees -> dinv
    k_init_deg<<<(NN + TB - 1) / TB, TB>>>();
    k_count<<<(EE + TB - 1) / TB, TB>>>(e1, 0);
    k_count<<<(EE + TB - 1) / TB, TB>>>(e2, 1);
    k_rsqrt<<<(2 * NN + TB - 1) / TB, TB>>>();

    // 4 masked GEMMs
    int gemmGrid = (NN + 63) / 64;
    k_gemm<<<gemmGrid, TB>>>(x, mp1, nullptr, W1, 0);
    k_gemm<<<gemmGrid, TB>>>(x, mn1, perm1,  W1, 1);
    k_gemm<<<gemmGrid, TB>>>(x, mp2, nullptr, W2, 2);
    k_gemm<<<gemmGrid, TB>>>(x, mn2, perm2,  W2, 3);

    // self-loop contributions initialize every output element
    int siGrid = (NN * 32 + TB - 1) / TB;
    k_selfinit<<<siGrid, TB>>>(0, p1, n1);
    k_selfinit<<<siGrid, TB>>>(1, p2, n2);

    // edge scatter (warp per edge)
    int scGrid = (EE * 32 + TB - 1) / TB;
    k_scatter<<<scGrid, TB>>>(e1, 0, p1, n1);
    k_scatter<<<scGrid, TB>>>(e2, 1, p2, n2);

    // summaries
    k_zeros<<<1, TB>>>(s1, s2);

    // bias + relu (+ mean for pos branches)
    k_finalize<<<gemmGrid, TB>>>(p1, b1, s1, invN);
    k_finalize<<<gemmGrid, TB>>>(n1, b1, nullptr, 0.f);
    k_finalize<<<gemmGrid, TB>>>(p2, b2, s2, invN);
    k_finalize<<<gemmGrid, TB>>>(n2, b2, nullptr, 0.f);
}

// round 2
// speedup vs baseline: 1.5125x; 1.5125x over previous
#include <cuda_runtime.h>
#include <cstdint>

#define NN 50000
#define DD 128
#define EE 800000
#define ND (NN*DD)
#define NB 196          // ceil(50000/256)

// Scratch (__device__ globals are the sanctioned mechanism).
__device__ float g_xw[4][ND];          // pos1, neg1, pos2, neg2  (x.*mask)[perm] @ W
__device__ float g_dinv[2][NN];        // rsqrt(deg) per branch
__device__ int   g_counts[2][NN];      // in-degree (excl. self loop)
__device__ int   g_offs[2][NN];        // CSR offsets
__device__ int   g_cursor[2][NN];      // fill cursors
__device__ int   g_srcSorted[2][EE];   // src ids sorted by dst
__device__ int   g_blockSums[2][256];  // scan partials (NB used)

// ---------------------------------------------------------------------------
// zero counts + summaries
// ---------------------------------------------------------------------------
__global__ void k_zero(float* s1, float* s2) {
    int i = blockIdx.x * blockDim.x + threadIdx.x;
    if (i < 2 * NN) (&g_counts[0][0])[i] = 0;
    if (i < DD) { s1[i] = 0.f; s2[i] = 0.f; }
}

__global__ void k_count(const int* __restrict__ ei, int b) {
    int e = blockIdx.x * blockDim.x + threadIdx.x;
    if (e < EE) atomicAdd(&g_counts[b][ei[EE + e]], 1);
}

__global__ void k_dinv() {
    int i = blockIdx.x * blockDim.x + threadIdx.x;
    if (i < 2 * NN)
        (&g_dinv[0][0])[i] = rsqrtf(1.0f + (float)(&g_counts[0][0])[i]);
}

// ---------------------------------------------------------------------------
// Masked (optionally row-permuted) GEMM:  g_xw[outIdx] = (x .* mask)[perm] @ W
// 64 rows x 128 cols per 256-thread block; near the FFMA-pipe floor.
// ---------------------------------------------------------------------------
__global__ __launch_bounds__(256) void k_gemm(const float* __restrict__ x,
                                              const float* __restrict__ mask,
                                              const int* __restrict__ perm,
                                              const float* __restrict__ W,
                                              int outIdx) {
    __shared__ float Ws[32 * 128];
    __shared__ float As[64 * 32];
    float4* Ws4 = reinterpret_cast<float4*>(Ws);
    float4* As4 = reinterpret_cast<float4*>(As);
    const float4* x4 = reinterpret_cast<const float4*>(x);
    const float4* m4 = reinterpret_cast<const float4*>(mask);
    const float4* W4 = reinterpret_cast<const float4*>(W);
    float4* out4 = reinterpret_cast<float4*>(g_xw[outIdx]);

    const int tid = threadIdx.x;
    const int c = tid & 31;
    const int g = tid >> 5;
    const int row0 = blockIdx.x * 64;

    float4 acc[8];
    #pragma unroll
    for (int r = 0; r < 8; r++) acc[r] = make_float4(0.f, 0.f, 0.f, 0.f);

    for (int kc = 0; kc < 128; kc += 32) {
        #pragma unroll
        for (int j = 0; j < 4; j++) {
            int idx = tid + 256 * j;
            int kk = idx >> 5, c4 = idx & 31;
            Ws4[idx] = W4[(kc + kk) * 32 + c4];
        }
        #pragma unroll
        for (int j = 0; j < 2; j++) {
            int idx = tid + 256 * j;
            int r = idx >> 3, c4 = idx & 7;
            int gi = row0 + r;
            float4 v = make_float4(0.f, 0.f, 0.f, 0.f);
            if (gi < NN) {
                int srow = perm ? perm[gi] : gi;
                int base = srow * 32 + (kc >> 2) + c4;
                float4 xv = x4[base];
                float4 mv = m4[base];
                v.x = xv.x * mv.x; v.y = xv.y * mv.y;
                v.z = xv.z * mv.z; v.w = xv.w * mv.w;
            }
            As4[idx] = v;
        }
        __syncthreads();
        #pragma unroll
        for (int k = 0; k < 32; k++) {
            float4 w = Ws4[k * 32 + c];
            #pragma unroll
            for (int r = 0; r < 8; r++) {
                float a = As[(8 * g + r) * 32 + k];
                acc[r].x += a * w.x; acc[r].y += a * w.y;
                acc[r].z += a * w.z; acc[r].w += a * w.w;
            }
        }
        __syncthreads();
    }
    #pragma unroll
    for (int r = 0; r < 8; r++) {
        int gi = row0 + 8 * g + r;
        if (gi < NN) out4[gi * 32 + c] = acc[r];
    }
}

// ---------------------------------------------------------------------------
// Counting-sort edges by dst: 2-level exclusive scan + atomic cursor fill.
// ---------------------------------------------------------------------------
__global__ void k_scan1() {
    __shared__ int sh[256];
    int b = blockIdx.y;
    int tid = threadIdx.x;
    int i = blockIdx.x * 256 + tid;
    int c = (i < NN) ? g_counts[b][i] : 0;
    sh[tid] = c;
    __syncthreads();
    #pragma unroll
    for (int off = 1; off < 256; off <<= 1) {
        int v = (tid >= off) ? sh[tid - off] : 0;
        __syncthreads();
        sh[tid] += v;
        __syncthreads();
    }
    if (i < NN) g_offs[b][i] = sh[tid] - c;          // exclusive within block
    if (tid == 255) g_blockSums[b][blockIdx.x] = sh[255];
}

__global__ void k_scan2() {
    __shared__ int sh[256];
    int b = blockIdx.x;
    int tid = threadIdx.x;
    int v = (tid < NB) ? g_blockSums[b][tid] : 0;
    sh[tid] = v;
    __syncthreads();
    #pragma unroll
    for (int off = 1; off < 256; off <<= 1) {
        int u = (tid >= off) ? sh[tid - off] : 0;
        __syncthreads();
        sh[tid] += u;
        __syncthreads();
    }
    g_blockSums[b][tid] = sh[tid] - v;               // exclusive block offsets
}

__global__ void k_scan3() {
    int b = blockIdx.y;
    int i = blockIdx.x * 256 + threadIdx.x;
    if (i < NN) {
        int o = g_offs[b][i] + g_blockSums[b][blockIdx.x];
        g_offs[b][i] = o;
        g_cursor[b][i] = o;
    }
}

__global__ void k_fill(const int* __restrict__ ei, int b) {
    int e = blockIdx.x * blockDim.x + threadIdx.x;
    if (e < EE) {
        int s = ei[e];
        int d = ei[EE + e];
        int p = atomicAdd(&g_cursor[b][d], 1);
        g_srcSorted[b][p] = s;
    }
}

// ---------------------------------------------------------------------------
// CSR aggregation, fully fused: per dst node (1 warp), accumulate self loop +
// all incoming messages for BOTH pos and neg arrays, add bias, ReLU, store
// once, and fold the pos-branch column mean into summary.
// 256 threads = 8 nodes/block; 6250 blocks = 50000 nodes exactly.
// ---------------------------------------------------------------------------
__global__ __launch_bounds__(256) void k_agg(int b,
                                             float* __restrict__ outp,
                                             float* __restrict__ outn,
                                             const float* __restrict__ bias,
                                             float* __restrict__ summary,
                                             float invN) {
    __shared__ float ssum[DD];
    const int tid = threadIdx.x;
    const int lane = tid & 31;
    const int w = tid >> 5;
    const int i = blockIdx.x * 8 + w;

    if (tid < DD) ssum[tid] = 0.f;

    const float4* xp = reinterpret_cast<const float4*>(g_xw[2 * b]);
    const float4* xn = reinterpret_cast<const float4*>(g_xw[2 * b + 1]);

    const float di = g_dinv[b][i];
    const float sself = di * di;
    float4 ap = xp[i * 32 + lane];
    float4 an = xn[i * 32 + lane];
    ap.x *= sself; ap.y *= sself; ap.z *= sself; ap.w *= sself;
    an.x *= sself; an.y *= sself; an.z *= sself; an.w *= sself;

    const int beg = g_offs[b][i];
    const int end = beg + g_counts[b][i];
    #pragma unroll 2
    for (int e = beg; e < end; e++) {
        int s = g_srcSorted[b][e];
        float nrm = g_dinv[b][s] * di;
        float4 vp = xp[s * 32 + lane];
        float4 vn = xn[s * 32 + lane];
        ap.x += vp.x * nrm; ap.y += vp.y * nrm;
        ap.z += vp.z * nrm; ap.w += vp.w * nrm;
        an.x += vn.x * nrm; an.y += vn.y * nrm;
        an.z += vn.z * nrm; an.w += vn.w * nrm;
    }

    const float4 bv = reinterpret_cast<const float4*>(bias)[lane];
    ap.x = fmaxf(ap.x + bv.x, 0.f); ap.y = fmaxf(ap.y + bv.y, 0.f);
    ap.z = fmaxf(ap.z + bv.z, 0.f); ap.w = fmaxf(ap.w + bv.w, 0.f);
    an.x = fmaxf(an.x + bv.x, 0.f); an.y = fmaxf(an.y + bv.y, 0.f);
    an.z = fmaxf(an.z + bv.z, 0.f); an.w = fmaxf(an.w + bv.w, 0.f);

    reinterpret_cast<float4*>(outp)[i * 32 + lane] = ap;
    reinterpret_cast<float4*>(outn)[i * 32 + lane] = an;

    __syncthreads();
    atomicAdd(&ssum[4 * lane + 0], ap.x);
    atomicAdd(&ssum[4 * lane + 1], ap.y);
    atomicAdd(&ssum[4 * lane + 2], ap.z);
    atomicAdd(&ssum[4 * lane + 3], ap.w);
    __syncthreads();
    if (tid < DD) atomicAdd(&summary[tid], ssum[tid] * invN);
}

// ---------------------------------------------------------------------------
extern "C" void kernel_launch(void* const* d_in, const int* in_sizes, int n_in,
                              void* d_out, int out_size) {
    const float* x   = (const float*)d_in[0];
    const float* W1  = (const float*)d_in[1];
    const float* b1  = (const float*)d_in[2];
    const float* W2  = (const float*)d_in[3];
    const float* b2  = (const float*)d_in[4];
    const float* mp1 = (const float*)d_in[5];
    const float* mn1 = (const float*)d_in[6];
    const float* mp2 = (const float*)d_in[7];
    const float* mn2 = (const float*)d_in[8];
    const int* e1    = (const int*)d_in[9];
    const int* e2    = (const int*)d_in[10];
    const int* perm1 = (const int*)d_in[11];
    const int* perm2 = (const int*)d_in[12];

    float* out = (float*)d_out;
    float* p1 = out;
    float* n1 = p1 + ND;
    float* s1 = n1 + ND;
    float* p2 = s1 + DD;
    float* n2 = p2 + ND;
    float* s2 = n2 + ND;

    const float invN = 1.0f / (float)NN;
    const int TB = 256;

    // degrees (launch order puts a GEMM at ncu's -s 5 capture slot)
    k_zero<<<(2 * NN + TB - 1) / TB, TB>>>(s1, s2);
    k_count<<<(EE + TB - 1) / TB, TB>>>(e1, 0);
    k_count<<<(EE + TB - 1) / TB, TB>>>(e2, 1);
    k_dinv<<<(2 * NN + TB - 1) / TB, TB>>>();

    // 4 masked GEMMs
    int gemmGrid = (NN + 63) / 64;
    k_gemm<<<gemmGrid, TB>>>(x, mp1, nullptr, W1, 0);
    k_gemm<<<gemmGrid, TB>>>(x, mn1, perm1,  W1, 1);
    k_gemm<<<gemmGrid, TB>>>(x, mp2, nullptr, W2, 2);
    k_gemm<<<gemmGrid, TB>>>(x, mn2, perm2,  W2, 3);

    // counting sort by dst
    dim3 scanGrid(NB, 2);
    k_scan1<<<scanGrid, TB>>>();
    k_scan2<<<2, TB>>>();
    k_scan3<<<scanGrid, TB>>>();
    k_fill<<<(EE + TB - 1) / TB, TB>>>(e1, 0);
    k_fill<<<(EE + TB - 1) / TB, TB>>>(e2, 1);

    // fused CSR aggregation + bias + ReLU + summary
    k_agg<<<NN / 8, TB>>>(0, p1, n1, b1, s1, invN);
    k_agg<<<NN / 8, TB>>>(1, p2, n2, b2, s2, invN);
}

// round 3
// speedup vs baseline: 1.8145x; 1.1997x over previous
#include <cuda_runtime.h>
#include <cstdint>

#define NN 50000
#define DD 128
#define EE 800000
#define ND (NN*DD)
#define NB 196          // ceil(50000/256)

// Scratch (__device__ globals are the sanctioned mechanism).
__device__ float g_xw[4][ND];          // pos1, neg1, pos2, neg2
__device__ float g_dinv[2][NN];
__device__ int   g_counts[2][NN];
__device__ int   g_offs[2][NN];
__device__ int   g_cursor[2][NN];
__device__ int   g_srcSorted[2][EE];
__device__ int   g_blockSums[2][256];

// ---------------------------------------------------------------------------
__global__ void k_zero(float* s1, float* s2) {
    int i = blockIdx.x * blockDim.x + threadIdx.x;
    if (i < 2 * NN) (&g_counts[0][0])[i] = 0;
    if (i < DD) { s1[i] = 0.f; s2[i] = 0.f; }
}

__global__ void k_count(const int* __restrict__ ei, int b) {
    int e = blockIdx.x * blockDim.x + threadIdx.x;
    if (e < EE) atomicAdd(&g_counts[b][ei[EE + e]], 1);
}

__global__ void k_dinv() {
    int i = blockIdx.x * blockDim.x + threadIdx.x;
    if (i < 2 * NN)
        (&g_dinv[0][0])[i] = rsqrtf(1.0f + (float)(&g_counts[0][0])[i]);
}

// ---------------------------------------------------------------------------
// TF32 tensor-core GEMM: g_xw[b] = (x .* mask_b)[perm_b] @ W_b
// One launch covers all 4 GEMMs via blockIdx.y.
// Tile 128x128 per 256-thread block; K chunked by 32.
// ---------------------------------------------------------------------------
__device__ __forceinline__ unsigned f2tf32(float f) {
    unsigned u;
    asm("cvt.rna.tf32.f32 %0, %1;" : "=r"(u) : "f"(f));
    return u;
}

#define AS_STRIDE 36    // 32 + 4  -> A frag banks (4g+tig) unique
#define WS_STRIDE 136   // 128 + 8 -> B frag banks (8tig+8nt+g) unique

__global__ __launch_bounds__(256, 2) void k_gemm_tf32(
        const float* __restrict__ x,
        const float* __restrict__ mp1, const float* __restrict__ mn1,
        const float* __restrict__ mp2, const float* __restrict__ mn2,
        const float* __restrict__ W1,  const float* __restrict__ W2,
        const int* __restrict__ perm1, const int* __restrict__ perm2) {
    __shared__ unsigned As[128 * AS_STRIDE];
    __shared__ unsigned Ws[32 * WS_STRIDE];

    const int b = blockIdx.y;
    const float* mask = (b == 0) ? mp1 : (b == 1) ? mn1 : (b == 2) ? mp2 : mn2;
    const float* W    = (b < 2) ? W1 : W2;
    const int*  perm  = (b == 1) ? perm1 : (b == 3) ? perm2 : nullptr;
    float* out = g_xw[b];

    const int tid  = threadIdx.x;
    const int w    = tid >> 5;
    const int lane = tid & 31;
    const int g    = lane >> 2;    // group id (row within frag)
    const int tig  = lane & 3;     // thread in group
    const int row0 = blockIdx.x * 128;

    const float4* x4 = reinterpret_cast<const float4*>(x);
    const float4* m4 = reinterpret_cast<const float4*>(mask);
    const float4* W4 = reinterpret_cast<const float4*>(W);

    float acc[16][4];
    #pragma unroll
    for (int nt = 0; nt < 16; nt++)
        #pragma unroll
        for (int j = 0; j < 4; j++) acc[nt][j] = 0.f;

    for (int kc = 0; kc < 128; kc += 32) {
        // W chunk [32 k][128 n] -> Ws (tf32), 1024 float4
        #pragma unroll
        for (int j = 0; j < 4; j++) {
            int idx = tid + 256 * j;
            int kk = idx >> 5, c4 = idx & 31;
            float4 v = W4[(kc + kk) * 32 + c4];
            unsigned* dst = &Ws[kk * WS_STRIDE + 4 * c4];
            dst[0] = f2tf32(v.x); dst[1] = f2tf32(v.y);
            dst[2] = f2tf32(v.z); dst[3] = f2tf32(v.w);
        }
        // A chunk [128 m][32 k] -> As (tf32, masked, optional perm), 1024 float4
        #pragma unroll
        for (int j = 0; j < 4; j++) {
            int idx = tid + 256 * j;
            int r = idx >> 3, c4 = idx & 7;
            int gi = row0 + r;
            unsigned* dst = &As[r * AS_STRIDE + 4 * c4];
            if (gi < NN) {
                int srow = perm ? perm[gi] : gi;
                int base = srow * 32 + (kc >> 2) + c4;
                float4 xv = x4[base];
                float4 mv = m4[base];
                dst[0] = f2tf32(xv.x * mv.x); dst[1] = f2tf32(xv.y * mv.y);
                dst[2] = f2tf32(xv.z * mv.z); dst[3] = f2tf32(xv.w * mv.w);
            } else {
                dst[0] = 0u; dst[1] = 0u; dst[2] = 0u; dst[3] = 0u;
            }
        }
        __syncthreads();

        #pragma unroll
        for (int ks = 0; ks < 4; ks++) {
            const int k0 = 8 * ks;
            unsigned a0 = As[(16 * w + g)     * AS_STRIDE + k0 + tig];
            unsigned a1 = As[(16 * w + g + 8) * AS_STRIDE + k0 + tig];
            unsigned a2 = As[(16 * w + g)     * AS_STRIDE + k0 + tig + 4];
            unsigned a3 = As[(16 * w + g + 8) * AS_STRIDE + k0 + tig + 4];
            #pragma unroll
            for (int nt = 0; nt < 16; nt++) {
                unsigned b0 = Ws[(k0 + tig)     * WS_STRIDE + 8 * nt + g];
                unsigned b1 = Ws[(k0 + tig + 4) * WS_STRIDE + 8 * nt + g];
                asm volatile(
                    "mma.sync.aligned.m16n8k8.row.col.f32.tf32.tf32.f32 "
                    "{%0,%1,%2,%3}, {%4,%5,%6,%7}, {%8,%9}, {%0,%1,%2,%3};"
                    : "+f"(acc[nt][0]), "+f"(acc[nt][1]),
                      "+f"(acc[nt][2]), "+f"(acc[nt][3])
                    : "r"(a0), "r"(a1), "r"(a2), "r"(a3), "r"(b0), "r"(b1));
            }
        }
        __syncthreads();
    }

    // Store: c0,c1 -> (row, 2tig) ; c2,c3 -> (row+8, 2tig)
    const int rA = row0 + 16 * w + g;
    const int rB = rA + 8;
    #pragma unroll
    for (int nt = 0; nt < 16; nt++) {
        int col = 8 * nt + 2 * tig;
        if (rA < NN)
            *reinterpret_cast<float2*>(&out[rA * DD + col]) =
                make_float2(acc[nt][0], acc[nt][1]);
        if (rB < NN)
            *reinterpret_cast<float2*>(&out[rB * DD + col]) =
                make_float2(acc[nt][2], acc[nt][3]);
    }
}

// ---------------------------------------------------------------------------
// Counting-sort edges by dst
// ---------------------------------------------------------------------------
__global__ void k_scan1() {
    __shared__ int sh[256];
    int b = blockIdx.y;
    int tid = threadIdx.x;
    int i = blockIdx.x * 256 + tid;
    int c = (i < NN) ? g_counts[b][i] : 0;
    sh[tid] = c;
    __syncthreads();
    #pragma unroll
    for (int off = 1; off < 256; off <<= 1) {
        int v = (tid >= off) ? sh[tid - off] : 0;
        __syncthreads();
        sh[tid] += v;
        __syncthreads();
    }
    if (i < NN) g_offs[b][i] = sh[tid] - c;
    if (tid == 255) g_blockSums[b][blockIdx.x] = sh[255];
}

__global__ void k_scan2() {
    __shared__ int sh[256];
    int b = blockIdx.x;
    int tid = threadIdx.x;
    int v = (tid < NB) ? g_blockSums[b][tid] : 0;
    sh[tid] = v;
    __syncthreads();
    #pragma unroll
    for (int off = 1; off < 256; off <<= 1) {
        int u = (tid >= off) ? sh[tid - off] : 0;
        __syncthreads();
        sh[tid] += u;
        __syncthreads();
    }
    g_blockSums[b][tid] = sh[tid] - v;
}

__global__ void k_scan3() {
    int b = blockIdx.y;
    int i = blockIdx.x * 256 + threadIdx.x;
    if (i < NN) {
        int o = g_offs[b][i] + g_blockSums[b][blockIdx.x];
        g_offs[b][i] = o;
        g_cursor[b][i] = o;
    }
}

__global__ void k_fill(const int* __restrict__ ei, int b) {
    int e = blockIdx.x * blockDim.x + threadIdx.x;
    if (e < EE) {
        int s = ei[e];
        int d = ei[EE + e];
        int p = atomicAdd(&g_cursor[b][d], 1);
        g_srcSorted[b][p] = s;
    }
}

// ---------------------------------------------------------------------------
// Fused CSR aggregation + bias + ReLU + summary. One warp per dst node.
// ---------------------------------------------------------------------------
__global__ __launch_bounds__(256) void k_agg(int b,
                                             float* __restrict__ outp,
                                             float* __restrict__ outn,
                                             const float* __restrict__ bias,
                                             float* __restrict__ summary,
                                             float invN) {
    __shared__ float ssum[DD];
    const int tid = threadIdx.x;
    const int lane = tid & 31;
    const int w = tid >> 5;
    const int i = blockIdx.x * 8 + w;

    if (tid < DD) ssum[tid] = 0.f;

    const float4* xp = reinterpret_cast<const float4*>(g_xw[2 * b]);
    const float4* xn = reinterpret_cast<const float4*>(g_xw[2 * b + 1]);

    const float di = g_dinv[b][i];
    const float sself = di * di;
    float4 ap = xp[i * 32 + lane];
    float4 an = xn[i * 32 + lane];
    ap.x *= sself; ap.y *= sself; ap.z *= sself; ap.w *= sself;
    an.x *= sself; an.y *= sself; an.z *= sself; an.w *= sself;

    const int beg = g_offs[b][i];
    const int end = beg + g_counts[b][i];
    #pragma unroll 2
    for (int e = beg; e < end; e++) {
        int s = g_srcSorted[b][e];
        float nrm = g_dinv[b][s] * di;
        float4 vp = xp[s * 32 + lane];
        float4 vn = xn[s * 32 + lane];
        ap.x += vp.x * nrm; ap.y += vp.y * nrm;
        ap.z += vp.z * nrm; ap.w += vp.w * nrm;
        an.x += vn.x * nrm; an.y += vn.y * nrm;
        an.z += vn.z * nrm; an.w += vn.w * nrm;
    }

    const float4 bv = reinterpret_cast<const float4*>(bias)[lane];
    ap.x = fmaxf(ap.x + bv.x, 0.f); ap.y = fmaxf(ap.y + bv.y, 0.f);
    ap.z = fmaxf(ap.z + bv.z, 0.f); ap.w = fmaxf(ap.w + bv.w, 0.f);
    an.x = fmaxf(an.x + bv.x, 0.f); an.y = fmaxf(an.y + bv.y, 0.f);
    an.z = fmaxf(an.z + bv.z, 0.f); an.w = fmaxf(an.w + bv.w, 0.f);

    reinterpret_cast<float4*>(outp)[i * 32 + lane] = ap;
    reinterpret_cast<float4*>(outn)[i * 32 + lane] = an;

    __syncthreads();
    atomicAdd(&ssum[4 * lane + 0], ap.x);
    atomicAdd(&ssum[4 * lane + 1], ap.y);
    atomicAdd(&ssum[4 * lane + 2], ap.z);
    atomicAdd(&ssum[4 * lane + 3], ap.w);
    __syncthreads();
    if (tid < DD) atomicAdd(&summary[tid], ssum[tid] * invN);
}

// ---------------------------------------------------------------------------
extern "C" void kernel_launch(void* const* d_in, const int* in_sizes, int n_in,
                              void* d_out, int out_size) {
    const float* x   = (const float*)d_in[0];
    const float* W1  = (const float*)d_in[1];
    const float* b1  = (const float*)d_in[2];
    const float* W2  = (const float*)d_in[3];
    const float* b2  = (const float*)d_in[4];
    const float* mp1 = (const float*)d_in[5];
    const float* mn1 = (const float*)d_in[6];
    const float* mp2 = (const float*)d_in[7];
    const float* mn2 = (const float*)d_in[8];
    const int* e1    = (const int*)d_in[9];
    const int* e2    = (const int*)d_in[10];
    const int* perm1 = (const int*)d_in[11];
    const int* perm2 = (const int*)d_in[12];

    float* out = (float*)d_out;
    float* p1 = out;
    float* n1 = p1 + ND;
    float* s1 = n1 + ND;
    float* p2 = s1 + DD;
    float* n2 = p2 + ND;
    float* s2 = n2 + ND;

    const float invN = 1.0f / (float)NN;
    const int TB = 256;

    k_zero<<<(2 * NN + TB - 1) / TB, TB>>>(s1, s2);
    k_count<<<(EE + TB - 1) / TB, TB>>>(e1, 0);
    k_count<<<(EE + TB - 1) / TB, TB>>>(e2, 1);
    k_dinv<<<(2 * NN + TB - 1) / TB, TB>>>();

    // all 4 GEMMs, tensor cores, one launch
    dim3 gemmGrid((NN + 127) / 128, 4);
    k_gemm_tf32<<<gemmGrid, TB>>>(x, mp1, mn1, mp2, mn2, W1, W2, perm1, perm2);

    // counting sort by dst
    dim3 scanGrid(NB, 2);
    k_scan1<<<scanGrid, TB>>>();
    k_scan2<<<2, TB>>>();
    k_scan3<<<scanGrid, TB>>>();
    k_fill<<<(EE + TB - 1) / TB, TB>>>(e1, 0);
    k_fill<<<(EE + TB - 1) / TB, TB>>>(e2, 1);

    // fused CSR aggregation + bias + ReLU + summary
    k_agg<<<NN / 8, TB>>>(0, p1, n1, b1, s1, invN);
    k_agg<<<NN / 8, TB>>>(1, p2, n2, b2, s2, invN);
}

// round 4
// speedup vs baseline: 2.2446x; 1.2370x over previous
#include <cuda_runtime.h>
#include <cuda_fp16.h>
#include <cstdint>

#define NN 50000
#define DD 128
#define EE 800000
#define ND (NN*DD)
#define NB 196          // ceil(50000/256)

// Scratch (__device__ globals are the sanctioned mechanism).
__device__ __half g_xw[4][ND];         // fp16 intermediates: pos1, neg1, pos2, neg2
__device__ float g_dinv[2][NN];
__device__ int   g_counts[2][NN];
__device__ int   g_offs[2][NN];
__device__ int   g_cursor[2][NN];
__device__ int2  g_edge[2][EE];        // {src, norm bits}, sorted by dst
__device__ int   g_blockSums[2][256];

// ---------------------------------------------------------------------------
__global__ void k_zero(float* s1, float* s2) {
    int i = blockIdx.x * blockDim.x + threadIdx.x;
    if (i < 2 * NN) (&g_counts[0][0])[i] = 0;
    if (i < DD) { s1[i] = 0.f; s2[i] = 0.f; }
}

__global__ void k_count(const int* __restrict__ e1, const int* __restrict__ e2) {
    int b = blockIdx.y;
    const int* ei = b ? e2 : e1;
    int e = blockIdx.x * blockDim.x + threadIdx.x;
    if (e < EE) atomicAdd(&g_counts[b][ei[EE + e]], 1);
}

// ---------------------------------------------------------------------------
// TF32 tensor-core GEMM: g_xw[b] = (x .* mask_b)[perm_b] @ W_b   (fp16 out)
// ---------------------------------------------------------------------------
__device__ __forceinline__ unsigned f2tf32(float f) {
    unsigned u;
    asm("cvt.rna.tf32.f32 %0, %1;" : "=r"(u) : "f"(f));
    return u;
}

#define AS_STRIDE 36
#define WS_STRIDE 136

__global__ __launch_bounds__(256, 2) void k_gemm_tf32(
        const float* __restrict__ x,
        const float* __restrict__ mp1, const float* __restrict__ mn1,
        const float* __restrict__ mp2, const float* __restrict__ mn2,
        const float* __restrict__ W1,  const float* __restrict__ W2,
        const int* __restrict__ perm1, const int* __restrict__ perm2) {
    __shared__ unsigned As[128 * AS_STRIDE];
    __shared__ unsigned Ws[32 * WS_STRIDE];

    const int b = blockIdx.y;
    const float* mask = (b == 0) ? mp1 : (b == 1) ? mn1 : (b == 2) ? mp2 : mn2;
    const float* W    = (b < 2) ? W1 : W2;
    const int*  perm  = (b == 1) ? perm1 : (b == 3) ? perm2 : nullptr;
    __half* out = g_xw[b];

    const int tid  = threadIdx.x;
    const int w    = tid >> 5;
    const int lane = tid & 31;
    const int g    = lane >> 2;
    const int tig  = lane & 3;
    const int row0 = blockIdx.x * 128;

    const float4* x4 = reinterpret_cast<const float4*>(x);
    const float4* m4 = reinterpret_cast<const float4*>(mask);
    const float4* W4 = reinterpret_cast<const float4*>(W);

    float acc[16][4];
    #pragma unroll
    for (int nt = 0; nt < 16; nt++)
        #pragma unroll
        for (int j = 0; j < 4; j++) acc[nt][j] = 0.f;

    for (int kc = 0; kc < 128; kc += 32) {
        #pragma unroll
        for (int j = 0; j < 4; j++) {
            int idx = tid + 256 * j;
            int kk = idx >> 5, c4 = idx & 31;
            float4 v = W4[(kc + kk) * 32 + c4];
            unsigned* dst = &Ws[kk * WS_STRIDE + 4 * c4];
            dst[0] = f2tf32(v.x); dst[1] = f2tf32(v.y);
            dst[2] = f2tf32(v.z); dst[3] = f2tf32(v.w);
        }
        #pragma unroll
        for (int j = 0; j < 4; j++) {
            int idx = tid + 256 * j;
            int r = idx >> 3, c4 = idx & 7;
            int gi = row0 + r;
            unsigned* dst = &As[r * AS_STRIDE + 4 * c4];
            if (gi < NN) {
                int srow = perm ? perm[gi] : gi;
                int base = srow * 32 + (kc >> 2) + c4;
                float4 xv = x4[base];
                float4 mv = m4[base];
                dst[0] = f2tf32(xv.x * mv.x); dst[1] = f2tf32(xv.y * mv.y);
                dst[2] = f2tf32(xv.z * mv.z); dst[3] = f2tf32(xv.w * mv.w);
            } else {
                dst[0] = 0u; dst[1] = 0u; dst[2] = 0u; dst[3] = 0u;
            }
        }
        __syncthreads();

        #pragma unroll
        for (int ks = 0; ks < 4; ks++) {
            const int k0 = 8 * ks;
            unsigned a0 = As[(16 * w + g)     * AS_STRIDE + k0 + tig];
            unsigned a1 = As[(16 * w + g + 8) * AS_STRIDE + k0 + tig];
            unsigned a2 = As[(16 * w + g)     * AS_STRIDE + k0 + tig + 4];
            unsigned a3 = As[(16 * w + g + 8) * AS_STRIDE + k0 + tig + 4];
            #pragma unroll
            for (int nt = 0; nt < 16; nt++) {
                unsigned b0 = Ws[(k0 + tig)     * WS_STRIDE + 8 * nt + g];
                unsigned b1 = Ws[(k0 + tig + 4) * WS_STRIDE + 8 * nt + g];
                asm volatile(
                    "mma.sync.aligned.m16n8k8.row.col.f32.tf32.tf32.f32 "
                    "{%0,%1,%2,%3}, {%4,%5,%6,%7}, {%8,%9}, {%0,%1,%2,%3};"
                    : "+f"(acc[nt][0]), "+f"(acc[nt][1]),
                      "+f"(acc[nt][2]), "+f"(acc[nt][3])
                    : "r"(a0), "r"(a1), "r"(a2), "r"(a3), "r"(b0), "r"(b1));
            }
        }
        __syncthreads();
    }

    const int rA = row0 + 16 * w + g;
    const int rB = rA + 8;
    #pragma unroll
    for (int nt = 0; nt < 16; nt++) {
        int col = 8 * nt + 2 * tig;
        if (rA < NN)
            *reinterpret_cast<__half2*>(&out[rA * DD + col]) =
                __floats2half2_rn(acc[nt][0], acc[nt][1]);
        if (rB < NN)
            *reinterpret_cast<__half2*>(&out[rB * DD + col]) =
                __floats2half2_rn(acc[nt][2], acc[nt][3]);
    }
}

// ---------------------------------------------------------------------------
// Counting sort by dst (scan1 also produces dinv)
// ---------------------------------------------------------------------------
__global__ void k_scan1() {
    __shared__ int sh[256];
    int b = blockIdx.y;
    int tid = threadIdx.x;
    int i = blockIdx.x * 256 + tid;
    int c = (i < NN) ? g_counts[b][i] : 0;
    sh[tid] = c;
    __syncthreads();
    #pragma unroll
    for (int off = 1; off < 256; off <<= 1) {
        int v = (tid >= off) ? sh[tid - off] : 0;
        __syncthreads();
        sh[tid] += v;
        __syncthreads();
    }
    if (i < NN) {
        g_offs[b][i] = sh[tid] - c;
        g_dinv[b][i] = rsqrtf(1.0f + (float)c);
    }
    if (tid == 255) g_blockSums[b][blockIdx.x] = sh[255];
}

__global__ void k_scan2() {
    __shared__ int sh[256];
    int b = blockIdx.x;
    int tid = threadIdx.x;
    int v = (tid < NB) ? g_blockSums[b][tid] : 0;
    sh[tid] = v;
    __syncthreads();
    #pragma unroll
    for (int off = 1; off < 256; off <<= 1) {
        int u = (tid >= off) ? sh[tid - off] : 0;
        __syncthreads();
        sh[tid] += u;
        __syncthreads();
    }
    g_blockSums[b][tid] = sh[tid] - v;
}

__global__ void k_scan3() {
    int b = blockIdx.y;
    int i = blockIdx.x * 256 + threadIdx.x;
    if (i < NN) {
        int o = g_offs[b][i] + g_blockSums[b][blockIdx.x];
        g_offs[b][i] = o;
        g_cursor[b][i] = o;
    }
}

__global__ void k_fill(const int* __restrict__ e1, const int* __restrict__ e2) {
    int b = blockIdx.y;
    const int* ei = b ? e2 : e1;
    int e = blockIdx.x * blockDim.x + threadIdx.x;
    if (e < EE) {
        int s = ei[e];
        int d = ei[EE + e];
        float norm = g_dinv[b][s] * g_dinv[b][d];
        int p = atomicAdd(&g_cursor[b][d], 1);
        g_edge[b][p] = make_int2(s, __float_as_int(norm));
    }
}

// ---------------------------------------------------------------------------
// Fused CSR aggregation (fp16 gathers, fp32 accum) + bias + ReLU + summary.
// One warp per dst node; lane owns 4 consecutive features (8 bytes fp16).
// ---------------------------------------------------------------------------
__device__ __forceinline__ float4 h2f4(uint2 u) {
    float2 a = __half22float2(*reinterpret_cast<__half2*>(&u.x));
    float2 b = __half22float2(*reinterpret_cast<__half2*>(&u.y));
    return make_float4(a.x, a.y, b.x, b.y);
}

__global__ __launch_bounds__(256) void k_agg(
        float* __restrict__ p1, float* __restrict__ n1,
        float* __restrict__ p2, float* __restrict__ n2,
        const float* __restrict__ b1, const float* __restrict__ b2,
        float* __restrict__ s1, float* __restrict__ s2, float invN) {
    __shared__ float ssum[DD];
    const int b = blockIdx.y;
    float* outp = b ? p2 : p1;
    float* outn = b ? n2 : n1;
    const float* bias = b ? b2 : b1;
    float* summary = b ? s2 : s1;

    const int tid = threadIdx.x;
    const int lane = tid & 31;
    const int w = tid >> 5;
    const int i = blockIdx.x * 8 + w;

    if (tid < DD) ssum[tid] = 0.f;

    const uint2* xp = reinterpret_cast<const uint2*>(g_xw[2 * b]);
    const uint2* xn = reinterpret_cast<const uint2*>(g_xw[2 * b + 1]);

    const float di = g_dinv[b][i];
    const float sself = di * di;
    float4 ap = h2f4(xp[i * 32 + lane]);
    float4 an = h2f4(xn[i * 32 + lane]);
    ap.x *= sself; ap.y *= sself; ap.z *= sself; ap.w *= sself;
    an.x *= sself; an.y *= sself; an.z *= sself; an.w *= sself;

    const int beg = g_offs[b][i];
    const int end = beg + g_counts[b][i];
    #pragma unroll 2
    for (int e = beg; e < end; e++) {
        int2 ed = g_edge[b][e];
        float nrm = __int_as_float(ed.y);
        float4 vp = h2f4(xp[ed.x * 32 + lane]);
        float4 vn = h2f4(xn[ed.x * 32 + lane]);
        ap.x += vp.x * nrm; ap.y += vp.y * nrm;
        ap.z += vp.z * nrm; ap.w += vp.w * nrm;
        an.x += vn.x * nrm; an.y += vn.y * nrm;
        an.z += vn.z * nrm; an.w += vn.w * nrm;
    }

    const float4 bv = reinterpret_cast<const float4*>(bias)[lane];
    ap.x = fmaxf(ap.x + bv.x, 0.f); ap.y = fmaxf(ap.y + bv.y, 0.f);
    ap.z = fmaxf(ap.z + bv.z, 0.f); ap.w = fmaxf(ap.w + bv.w, 0.f);
    an.x = fmaxf(an.x + bv.x, 0.f); an.y = fmaxf(an.y + bv.y, 0.f);
    an.z = fmaxf(an.z + bv.z, 0.f); an.w = fmaxf(an.w + bv.w, 0.f);

    reinterpret_cast<float4*>(outp)[i * 32 + lane] = ap;
    reinterpret_cast<float4*>(outn)[i * 32 + lane] = an;

    __syncthreads();
    atomicAdd(&ssum[4 * lane + 0], ap.x);
    atomicAdd(&ssum[4 * lane + 1], ap.y);
    atomicAdd(&ssum[4 * lane + 2], ap.z);
    atomicAdd(&ssum[4 * lane + 3], ap.w);
    __syncthreads();
    if (tid < DD) atomicAdd(&summary[tid], ssum[tid] * invN);
}

// ---------------------------------------------------------------------------
extern "C" void kernel_launch(void* const* d_in, const int* in_sizes, int n_in,
                              void* d_out, int out_size) {
    const float* x   = (const float*)d_in[0];
    const float* W1  = (const float*)d_in[1];
    const float* b1  = (const float*)d_in[2];
    const float* W2  = (const float*)d_in[3];
    const float* b2  = (const float*)d_in[4];
    const float* mp1 = (const float*)d_in[5];
    const float* mn1 = (const float*)d_in[6];
    const float* mp2 = (const float*)d_in[7];
    const float* mn2 = (const float*)d_in[8];
    const int* e1    = (const int*)d_in[9];
    const int* e2    = (const int*)d_in[10];
    const int* perm1 = (const int*)d_in[11];
    const int* perm2 = (const int*)d_in[12];

    float* out = (float*)d_out;
    float* p1 = out;
    float* n1 = p1 + ND;
    float* s1 = n1 + ND;
    float* p2 = s1 + DD;
    float* n2 = p2 + ND;
    float* s2 = n2 + ND;

    const float invN = 1.0f / (float)NN;
    const int TB = 256;

    k_zero<<<(2 * NN + TB - 1) / TB, TB>>>(s1, s2);
    k_count<<<dim3((EE + TB - 1) / TB, 2), TB>>>(e1, e2);

    dim3 scanGrid(NB, 2);
    k_scan1<<<scanGrid, TB>>>();
    k_scan2<<<2, TB>>>();
    k_scan3<<<scanGrid, TB>>>();
    k_fill<<<dim3((EE + TB - 1) / TB, 2), TB>>>(e1, e2);

    dim3 gemmGrid((NN + 127) / 128, 4);
    k_gemm_tf32<<<gemmGrid, TB>>>(x, mp1, mn1, mp2, mn2, W1, W2, perm1, perm2);

    k_agg<<<dim3(NN / 8, 2), TB>>>(p1, n1, p2, n2, b1, b2, s1, s2, invN);
}

// round 5
// speedup vs baseline: 2.3521x; 1.0479x over previous
#include <cuda_runtime.h>
#include <cuda_fp16.h>
#include <cstdint>

#define NN 50000
#define DD 128
#define EE 800000
#define ND (NN*DD)
#define NB 196          // ceil(50000/256)

// Scratch (__device__ globals are the sanctioned mechanism).
__device__ __half g_xw[4][ND];         // fp16 intermediates: pos1, neg1, pos2, neg2
__device__ float g_dinv[2][NN];
__device__ int   g_counts[2][NN];
__device__ int   g_offs[2][NN];
__device__ int   g_cursor[2][NN];
__device__ int2  g_edge[2][EE];        // {src, norm bits}, sorted by dst
__device__ int   g_blockSums[2][256];

// ---------------------------------------------------------------------------
__global__ void k_zero(float* s1, float* s2) {
    int i = blockIdx.x * blockDim.x + threadIdx.x;
    if (i < 2 * NN) (&g_counts[0][0])[i] = 0;
    if (i < DD) { s1[i] = 0.f; s2[i] = 0.f; }
}

__global__ void k_count(const int* __restrict__ e1, const int* __restrict__ e2) {
    int b = blockIdx.y;
    const int* ei = b ? e2 : e1;
    int e = blockIdx.x * blockDim.x + threadIdx.x;
    if (e < EE) atomicAdd(&g_counts[b][ei[EE + e]], 1);
}

// ---------------------------------------------------------------------------
// FP16 tensor-core GEMM with ldmatrix: g_xw[b] = (x .* mask_b)[perm_b] @ W_b
// Tile 128x128 per 256-thread block, K chunked by 32; fp32 accumulate.
// ---------------------------------------------------------------------------
#define AS_H 40    // A row stride in halves (20 words; 5m mod 8 distinct)
#define WS_H 136   // W row stride in halves (68 words; 17k mod 8 distinct)

__device__ __forceinline__ unsigned smem_u32(const void* p) {
    return (unsigned)__cvta_generic_to_shared(p);
}
__device__ __forceinline__ void ldsm4(unsigned& r0, unsigned& r1,
                                      unsigned& r2, unsigned& r3, unsigned a) {
    asm volatile("ldmatrix.sync.aligned.m8n8.x4.shared.b16 {%0,%1,%2,%3}, [%4];"
                 : "=r"(r0), "=r"(r1), "=r"(r2), "=r"(r3) : "r"(a));
}
__device__ __forceinline__ void ldsm4t(unsigned& r0, unsigned& r1,
                                       unsigned& r2, unsigned& r3, unsigned a) {
    asm volatile("ldmatrix.sync.aligned.m8n8.x4.trans.shared.b16 {%0,%1,%2,%3}, [%4];"
                 : "=r"(r0), "=r"(r1), "=r"(r2), "=r"(r3) : "r"(a));
}

__global__ __launch_bounds__(256, 2) void k_gemm_f16(
        const float* __restrict__ x,
        const float* __restrict__ mp1, const float* __restrict__ mn1,
        const float* __restrict__ mp2, const float* __restrict__ mn2,
        const float* __restrict__ W1,  const float* __restrict__ W2,
        const int* __restrict__ perm1, const int* __restrict__ perm2) {
    __shared__ __half As[128 * AS_H];
    __shared__ __half Ws[32 * WS_H];

    const int b = blockIdx.y;
    const float* mask = (b == 0) ? mp1 : (b == 1) ? mn1 : (b == 2) ? mp2 : mn2;
    const float* W    = (b < 2) ? W1 : W2;
    const int*  perm  = (b == 1) ? perm1 : (b == 3) ? perm2 : nullptr;
    __half* out = g_xw[b];

    const int tid  = threadIdx.x;
    const int w    = tid >> 5;
    const int lane = tid & 31;
    const int g    = lane >> 2;
    const int tig  = lane & 3;
    const int row0 = blockIdx.x * 128;

    const float4* x4 = reinterpret_cast<const float4*>(x);
    const float4* m4 = reinterpret_cast<const float4*>(mask);
    const float4* W4 = reinterpret_cast<const float4*>(W);

    // per-lane ldmatrix base offsets (halves)
    const int a_row = 16 * w + (lane & 7) + ((lane >> 3) & 1) * 8;
    const int a_colbase = ((lane >> 4) & 1) * 8;
    const unsigned As_base = smem_u32(As);
    const unsigned Ws_base = smem_u32(Ws);
    const int b_krow = (lane & 7) + ((lane >> 3) & 1) * 8;   // k within step
    const int b_ncol = ((lane >> 4) & 1) * 8;                // n offset within pair

    float acc[16][4];
    #pragma unroll
    for (int nt = 0; nt < 16; nt++)
        #pragma unroll
        for (int j = 0; j < 4; j++) acc[nt][j] = 0.f;

    for (int kc = 0; kc < 128; kc += 32) {
        // W chunk [32 k][128 n] -> Ws fp16
        #pragma unroll
        for (int j = 0; j < 4; j++) {
            int idx = tid + 256 * j;
            int kk = idx >> 5, c4 = idx & 31;
            float4 v = W4[(kc + kk) * 32 + c4];
            __half2 h0 = __floats2half2_rn(v.x, v.y);
            __half2 h1 = __floats2half2_rn(v.z, v.w);
            *reinterpret_cast<__half2*>(&Ws[kk * WS_H + 4 * c4])     = h0;
            *reinterpret_cast<__half2*>(&Ws[kk * WS_H + 4 * c4 + 2]) = h1;
        }
        // A chunk [128 m][32 k] -> As fp16 (masked, optional perm)
        #pragma unroll
        for (int j = 0; j < 4; j++) {
            int idx = tid + 256 * j;
            int r = idx >> 3, c4 = idx & 7;
            int gi = row0 + r;
            __half2 h0, h1;
            if (gi < NN) {
                int srow = perm ? perm[gi] : gi;
                int base = srow * 32 + (kc >> 2) + c4;
                float4 xv = x4[base];
                float4 mv = m4[base];
                h0 = __floats2half2_rn(xv.x * mv.x, xv.y * mv.y);
                h1 = __floats2half2_rn(xv.z * mv.z, xv.w * mv.w);
            } else {
                h0 = __floats2half2_rn(0.f, 0.f);
                h1 = h0;
            }
            *reinterpret_cast<__half2*>(&As[r * AS_H + 4 * c4])     = h0;
            *reinterpret_cast<__half2*>(&As[r * AS_H + 4 * c4 + 2]) = h1;
        }
        __syncthreads();

        #pragma unroll
        for (int ks = 0; ks < 2; ks++) {
            const int kb = 16 * ks;
            unsigned a0, a1, a2, a3;
            ldsm4(a0, a1, a2, a3,
                  As_base + (a_row * AS_H + kb + a_colbase) * 2);
            #pragma unroll
            for (int nt2 = 0; nt2 < 8; nt2++) {
                unsigned b0, b1, b2, b3;
                ldsm4t(b0, b1, b2, b3,
                       Ws_base + ((kb + b_krow) * WS_H + 16 * nt2 + b_ncol) * 2);
                asm volatile(
                    "mma.sync.aligned.m16n8k16.row.col.f32.f16.f16.f32 "
                    "{%0,%1,%2,%3}, {%4,%5,%6,%7}, {%8,%9}, {%0,%1,%2,%3};"
                    : "+f"(acc[2*nt2][0]), "+f"(acc[2*nt2][1]),
                      "+f"(acc[2*nt2][2]), "+f"(acc[2*nt2][3])
                    : "r"(a0), "r"(a1), "r"(a2), "r"(a3), "r"(b0), "r"(b1));
                asm volatile(
                    "mma.sync.aligned.m16n8k16.row.col.f32.f16.f16.f32 "
                    "{%0,%1,%2,%3}, {%4,%5,%6,%7}, {%8,%9}, {%0,%1,%2,%3};"
                    : "+f"(acc[2*nt2+1][0]), "+f"(acc[2*nt2+1][1]),
                      "+f"(acc[2*nt2+1][2]), "+f"(acc[2*nt2+1][3])
                    : "r"(a0), "r"(a1), "r"(a2), "r"(a3), "r"(b2), "r"(b3));
            }
        }
        __syncthreads();
    }

    const int rA = row0 + 16 * w + g;
    const int rB = rA + 8;
    #pragma unroll
    for (int nt = 0; nt < 16; nt++) {
        int col = 8 * nt + 2 * tig;
        if (rA < NN)
            *reinterpret_cast<__half2*>(&out[rA * DD + col]) =
                __floats2half2_rn(acc[nt][0], acc[nt][1]);
        if (rB < NN)
            *reinterpret_cast<__half2*>(&out[rB * DD + col]) =
                __floats2half2_rn(acc[nt][2], acc[nt][3]);
    }
}

// ---------------------------------------------------------------------------
// Counting sort by dst (scan1 also produces dinv)
// ---------------------------------------------------------------------------
__global__ void k_scan1() {
    __shared__ int sh[256];
    int b = blockIdx.y;
    int tid = threadIdx.x;
    int i = blockIdx.x * 256 + tid;
    int c = (i < NN) ? g_counts[b][i] : 0;
    sh[tid] = c;
    __syncthreads();
    #pragma unroll
    for (int off = 1; off < 256; off <<= 1) {
        int v = (tid >= off) ? sh[tid - off] : 0;
        __syncthreads();
        sh[tid] += v;
        __syncthreads();
    }
    if (i < NN) {
        g_offs[b][i] = sh[tid] - c;
        g_dinv[b][i] = rsqrtf(1.0f + (float)c);
    }
    if (tid == 255) g_blockSums[b][blockIdx.x] = sh[255];
}

__global__ void k_scan2() {
    __shared__ int sh[256];
    int b = blockIdx.x;
    int tid = threadIdx.x;
    int v = (tid < NB) ? g_blockSums[b][tid] : 0;
    sh[tid] = v;
    __syncthreads();
    #pragma unroll
    for (int off = 1; off < 256; off <<= 1) {
        int u = (tid >= off) ? sh[tid - off] : 0;
        __syncthreads();
        sh[tid] += u;
        __syncthreads();
    }
    g_blockSums[b][tid] = sh[tid] - v;
}

__global__ void k_scan3() {
    int b = blockIdx.y;
    int i = blockIdx.x * 256 + threadIdx.x;
    if (i < NN) {
        int o = g_offs[b][i] + g_blockSums[b][blockIdx.x];
        g_offs[b][i] = o;
        g_cursor[b][i] = o;
    }
}

__global__ void k_fill(const int* __restrict__ e1, const int* __restrict__ e2) {
    int b = blockIdx.y;
    const int* ei = b ? e2 : e1;
    int e = blockIdx.x * blockDim.x + threadIdx.x;
    if (e < EE) {
        int s = ei[e];
        int d = ei[EE + e];
        float norm = g_dinv[b][s] * g_dinv[b][d];
        int p = atomicAdd(&g_cursor[b][d], 1);
        g_edge[b][p] = make_int2(s, __float_as_int(norm));
    }
}

// ---------------------------------------------------------------------------
// Fused CSR aggregation (fp16 gathers, fp32 accum) + bias + ReLU + summary.
// ---------------------------------------------------------------------------
__device__ __forceinline__ float4 h2f4(uint2 u) {
    float2 a = __half22float2(*reinterpret_cast<__half2*>(&u.x));
    float2 b = __half22float2(*reinterpret_cast<__half2*>(&u.y));
    return make_float4(a.x, a.y, b.x, b.y);
}

__global__ __launch_bounds__(256) void k_agg(
        float* __restrict__ p1, float* __restrict__ n1,
        float* __restrict__ p2, float* __restrict__ n2,
        const float* __restrict__ b1, const float* __restrict__ b2,
        float* __restrict__ s1, float* __restrict__ s2, float invN) {
    __shared__ float ssum[DD];
    const int b = blockIdx.y;
    float* outp = b ? p2 : p1;
    float* outn = b ? n2 : n1;
    const float* bias = b ? b2 : b1;
    float* summary = b ? s2 : s1;

    const int tid = threadIdx.x;
    const int lane = tid & 31;
    const int w = tid >> 5;
    const int i = blockIdx.x * 8 + w;

    if (tid < DD) ssum[tid] = 0.f;

    const uint2* xp = reinterpret_cast<const uint2*>(g_xw[2 * b]);
    const uint2* xn = reinterpret_cast<const uint2*>(g_xw[2 * b + 1]);

    const float di = g_dinv[b][i];
    const float sself = di * di;
    float4 ap = h2f4(xp[i * 32 + lane]);
    float4 an = h2f4(xn[i * 32 + lane]);
    ap.x *= sself; ap.y *= sself; ap.z *= sself; ap.w *= sself;
    an.x *= sself; an.y *= sself; an.z *= sself; an.w *= sself;

    const int beg = g_offs[b][i];
    const int end = beg + g_counts[b][i];
    #pragma unroll 2
    for (int e = beg; e < end; e++) {
        int2 ed = g_edge[b][e];
        float nrm = __int_as_float(ed.y);
        float4 vp = h2f4(xp[ed.x * 32 + lane]);
        float4 vn = h2f4(xn[ed.x * 32 + lane]);
        ap.x += vp.x * nrm; ap.y += vp.y * nrm;
        ap.z += vp.z * nrm; ap.w += vp.w * nrm;
        an.x += vn.x * nrm; an.y += vn.y * nrm;
        an.z += vn.z * nrm; an.w += vn.w * nrm;
    }

    const float4 bv = reinterpret_cast<const float4*>(bias)[lane];
    ap.x = fmaxf(ap.x + bv.x, 0.f); ap.y = fmaxf(ap.y + bv.y, 0.f);
    ap.z = fmaxf(ap.z + bv.z, 0.f); ap.w = fmaxf(ap.w + bv.w, 0.f);
    an.x = fmaxf(an.x + bv.x, 0.f); an.y = fmaxf(an.y + bv.y, 0.f);
    an.z = fmaxf(an.z + bv.z, 0.f); an.w = fmaxf(an.w + bv.w, 0.f);

    reinterpret_cast<float4*>(outp)[i * 32 + lane] = ap;
    reinterpret_cast<float4*>(outn)[i * 32 + lane] = an;

    __syncthreads();
    atomicAdd(&ssum[4 * lane + 0], ap.x);
    atomicAdd(&ssum[4 * lane + 1], ap.y);
    atomicAdd(&ssum[4 * lane + 2], ap.z);
    atomicAdd(&ssum[4 * lane + 3], ap.w);
    __syncthreads();
    if (tid < DD) atomicAdd(&summary[tid], ssum[tid] * invN);
}

// ---------------------------------------------------------------------------
extern "C" void kernel_launch(void* const* d_in, const int* in_sizes, int n_in,
                              void* d_out, int out_size) {
    const float* x   = (const float*)d_in[0];
    const float* W1  = (const float*)d_in[1];
    const float* b1  = (const float*)d_in[2];
    const float* W2  = (const float*)d_in[3];
    const float* b2  = (const float*)d_in[4];
    const float* mp1 = (const float*)d_in[5];
    const float* mn1 = (const float*)d_in[6];
    const float* mp2 = (const float*)d_in[7];
    const float* mn2 = (const float*)d_in[8];
    const int* e1    = (const int*)d_in[9];
    const int* e2    = (const int*)d_in[10];
    const int* perm1 = (const int*)d_in[11];
    const int* perm2 = (const int*)d_in[12];

    float* out = (float*)d_out;
    float* p1 = out;
    float* n1 = p1 + ND;
    float* s1 = n1 + ND;
    float* p2 = s1 + DD;
    float* n2 = p2 + ND;
    float* s2 = n2 + ND;

    const float invN = 1.0f / (float)NN;
    const int TB = 256;

    k_zero<<<(2 * NN + TB - 1) / TB, TB>>>(s1, s2);
    k_count<<<dim3((EE + TB - 1) / TB, 2), TB>>>(e1, e2);

    dim3 scanGrid(NB, 2);
    k_scan1<<<scanGrid, TB>>>();
    k_scan2<<<2, TB>>>();
    k_scan3<<<scanGrid, TB>>>();
    k_fill<<<dim3((EE + TB - 1) / TB, 2), TB>>>(e1, e2);

    dim3 gemmGrid((NN + 127) / 128, 4);
    k_gemm_f16<<<gemmGrid, TB>>>(x, mp1, mn1, mp2, mn2, W1, W2, perm1, perm2);

    k_agg<<<dim3(NN / 8, 2), TB>>>(p1, n1, p2, n2, b1, b2, s1, s2, invN);
}